// round 5
// baseline (speedup 1.0000x reference)
#include <cuda_runtime.h>
#include <cuda_bf16.h>
#include <math.h>

#define BATCH 2
#define LSEQ 4096
#define DMODEL 1024
#define NSTATE 16
#define RRANK 64
#define MROWS (BATCH * LSEQ)   /* 8192 */

// Scratch (static device globals — no allocation at runtime)
__device__ __align__(16) float  g_xconv[MROWS * DMODEL];    // (B,L,D)  32 MB
__device__ __align__(16) float2 g_xdt[MROWS * DMODEL];      // packed {x_conv, dt} 64 MB
__device__ __align__(16) float  g_tmp[MROWS * RRANK];       // (B*L, R)  2 MB
// per row: 8 groups of 4 floats: group n = {B_n, B_{n+8}, C_n, C_{n+8}}
__device__ __align__(16) float g_bc[MROWS * 32];            // 1 MB

// ---------------------------------------------------------------------------
// Kernel 1: fused [depthwise causal conv(K=4)+SiLU] + projection GEMM
//   out(8192 x 96) = silu(conv(x)) @ [W_dt1; W_B; W_C]^T
// Also side-writes g_xconv for gemm2's packing step.
// BM=64, BN=96, BK=32, 384 threads, thread tile 4x4 (16 x 24 thread grid)
// ---------------------------------------------------------------------------
__global__ __launch_bounds__(384) void gemm1_kernel(
        const float* __restrict__ x,
        const float* __restrict__ Wdt1,
        const float* __restrict__ WB,
        const float* __restrict__ WC,
        const float* __restrict__ conv_w,
        const float* __restrict__ conv_b) {
    __shared__ float Xs[67][33];                    // raw x rows (scalar access)
    __shared__ __align__(16) float As[32][68];      // [k][m] conv+silu (272B rows)
    __shared__ __align__(16) float Bs[32][104];     // [k][j] weights   (416B rows)

    int m0 = blockIdx.x * 64;
    int l0 = m0 % LSEQ;              // tile never crosses batch (64 | 4096)
    int tid = threadIdx.x;
    int tx = tid % 24;               // 24 col-groups * 4 = 96
    int ty = tid / 24;               // 16 row-groups * 4 = 64

    float acc[4][4];
#pragma unroll
    for (int i = 0; i < 4; i++)
#pragma unroll
        for (int j = 0; j < 4; j++) acc[i][j] = 0.0f;

    for (int kk = 0; kk < DMODEL; kk += 32) {
        // ---- stage raw x tile (67 rows x 32 cols) ----
        for (int e = tid; e < 67 * 32; e += 384) {
            int r = e >> 5, c = e & 31;
            float v = 0.0f;
            if (l0 + r - 3 >= 0)     // left causal pad at batch start
                v = x[(size_t)(m0 + r - 3) * DMODEL + kk + c];
            Xs[r][c] = v;
        }
        // ---- stage weights tile ----
        for (int e = tid; e < 96 * 32; e += 384) {
            int j = e >> 5, c = e & 31;
            float v;
            if (j < 64)      v = Wdt1[j * DMODEL + kk + c];
            else if (j < 80) v = WB[(j - 64) * DMODEL + kk + c];
            else             v = WC[(j - 80) * DMODEL + kk + c];
            Bs[c][j] = v;
        }
        __syncthreads();

        // ---- conv + silu into As; side-write g_xconv ----
        for (int e = tid; e < 64 * 32; e += 384) {
            int r = e >> 5, c = e & 31;
            int d = kk + c;
            float a = conv_b[d];
#pragma unroll
            for (int k = 0; k < 4; k++)
                a = fmaf(Xs[r + k][c], conv_w[d * 4 + k], a);
            float s = a / (1.0f + __expf(-a));
            As[c][r] = s;
            g_xconv[(size_t)(m0 + r) * DMODEL + d] = s;
        }
        __syncthreads();

        // ---- main FMA loop: vectorized smem reads ----
#pragma unroll
        for (int k = 0; k < 32; k++) {
            float4 a = *reinterpret_cast<const float4*>(&As[k][ty * 4]);
            float4 b = *reinterpret_cast<const float4*>(&Bs[k][tx * 4]);
            float av[4] = {a.x, a.y, a.z, a.w};
            float bv[4] = {b.x, b.y, b.z, b.w};
#pragma unroll
            for (int i = 0; i < 4; i++)
#pragma unroll
                for (int j = 0; j < 4; j++)
                    acc[i][j] = fmaf(av[i], bv[j], acc[i][j]);
        }
        __syncthreads();
    }

#pragma unroll
    for (int i = 0; i < 4; i++) {
        int row = m0 + ty * 4 + i;
#pragma unroll
        for (int j = 0; j < 4; j++) {
            int col = tx * 4 + j;
            float v = acc[i][j];
            if (col < 64) {
                g_tmp[row * RRANK + col] = v;
            } else if (col < 80) {
                int s = col - 64;   // B state s
                g_bc[row * 32 + (s & 7) * 4 + (s >> 3)] = v;
            } else {
                int s = col - 80;   // C state s
                g_bc[row * 32 + (s & 7) * 4 + 2 + (s >> 3)] = v;
            }
        }
    }
}

// ---------------------------------------------------------------------------
// Kernel 2: dt = softplus(g_tmp @ W_dt2^T + b_dt)   M=8192, N=1024, K=64
// Writes packed {x_conv, dt} into g_xdt with coalesced 16B stores.
// ---------------------------------------------------------------------------
__global__ void gemm2_kernel(const float* __restrict__ Wdt2,
                             const float* __restrict__ bdt) {
    __shared__ float As[64][65];    // [k][m]
    __shared__ float Bs[64][68];    // [k][d]

    int m0 = blockIdx.x * 64;
    int n0 = blockIdx.y * 64;
    int tid = threadIdx.x;
    int tx = tid % 16;
    int ty = tid / 16;

    for (int e = tid; e < 64 * 64; e += 256) {
        int r = e >> 6, c = e & 63;
        As[c][r] = g_tmp[(m0 + r) * RRANK + c];
        Bs[c][r] = Wdt2[(n0 + r) * RRANK + c];
    }
    __syncthreads();

    float acc[4][4];
#pragma unroll
    for (int i = 0; i < 4; i++)
#pragma unroll
        for (int j = 0; j < 4; j++) acc[i][j] = 0.0f;

#pragma unroll
    for (int k = 0; k < 64; k++) {
        float a[4], b[4];
#pragma unroll
        for (int i = 0; i < 4; i++) a[i] = As[k][ty * 4 + i];
#pragma unroll
        for (int j = 0; j < 4; j++) b[j] = Bs[k][tx * 4 + j];
#pragma unroll
        for (int i = 0; i < 4; i++)
#pragma unroll
            for (int j = 0; j < 4; j++)
                acc[i][j] = fmaf(a[i], b[j], acc[i][j]);
    }

#pragma unroll
    for (int i = 0; i < 4; i++) {
        int row = m0 + ty * 4 + i;
        int col0 = n0 + tx * 4;
        float4 xv = *reinterpret_cast<const float4*>(&g_xconv[row * DMODEL + col0]);
        float sp[4];
#pragma unroll
        for (int j = 0; j < 4; j++) {
            float z = acc[i][j] + bdt[col0 + j];
            sp[j] = fmaxf(z, 0.0f) + log1pf(__expf(-fabsf(z)));   // softplus
        }
        float4* dst = reinterpret_cast<float4*>(&g_xdt[row * DMODEL + col0]);
        dst[0] = make_float4(xv.x, sp[0], xv.y, sp[1]);
        dst[1] = make_float4(xv.z, sp[2], xv.w, sp[3]);
    }
}

// ---------------------------------------------------------------------------
// Kernel 3: selective scan.
// 8 lanes per channel, 2 states per thread (n and n+8) -> warp = 4 channels.
// 3-round butterfly (round-major), software-pipelined loads.
// 2048 channels -> 128 CTAs x 128 threads (512 warps).
// ---------------------------------------------------------------------------
#define SCAN_U 8

__global__ __launch_bounds__(128) void scan_kernel(
        const float* __restrict__ A_log,
        const float* __restrict__ Dp,
        float* __restrict__ out) {
    int tid = threadIdx.x;
    int lane = tid & 31;
    int warp = tid >> 5;
    int n = lane & 7;                      // state index (this thread: n, n+8)
    int c = blockIdx.x * 16 + warp * 4 + (lane >> 3);   // channel = b*D + d
    int b = c >> 10;
    int d = c & (DMODEL - 1);

    float A0 = -__expf(A_log[d * NSTATE + n]);
    float A1 = -__expf(A_log[d * NSTATE + n + 8]);
    float Dv = Dp[d];

    const float2* xdtp = g_xdt + (size_t)b * LSEQ * DMODEL + d;
    const float4* bcp  = reinterpret_cast<const float4*>(g_bc)
                         + (size_t)b * LSEQ * 8 + n;
    float* op = out + (size_t)b * LSEQ * DMODEL + d;

    float h0 = 0.0f, h1 = 0.0f;

    // prologue: prefetch tile 0
    float2 xn[SCAN_U];
    float4 bn[SCAN_U];
#pragma unroll
    for (int j = 0; j < SCAN_U; j++) {
        xn[j] = __ldg(xdtp + j * DMODEL);
        bn[j] = __ldg(bcp + j * 8);
    }
    xdtp += SCAN_U * DMODEL;
    bcp  += SCAN_U * 8;

    const int NTILES = LSEQ / SCAN_U;
    for (int t = 0; t < NTILES; t++) {
        float2 xc[SCAN_U];
        float4 bc[SCAN_U];
#pragma unroll
        for (int j = 0; j < SCAN_U; j++) { xc[j] = xn[j]; bc[j] = bn[j]; }

        if (t + 1 < NTILES) {
#pragma unroll
            for (int j = 0; j < SCAN_U; j++) {
                xn[j] = __ldg(xdtp + j * DMODEL);
                bn[j] = __ldg(bcp + j * 8);
            }
            xdtp += SCAN_U * DMODEL;
            bcp  += SCAN_U * 8;
        }

        // ---- phase 1: h recurrence for 2 states; p[j] = h0*C0 + h1*C1 ----
        float p[SCAN_U];
#pragma unroll
        for (int j = 0; j < SCAN_U; j++) {
            float xv  = xc[j].x;
            float dtv = xc[j].y;
            // exp(clip(dt*A,-10,0)) then min 0.999 (redundant clips dropped)
            float e0 = fminf(__expf(fmaxf(dtv * A0, -10.0f)), 0.999f);
            float e1 = fminf(__expf(fmaxf(dtv * A1, -10.0f)), 0.999f);
            float dtc = fminf(dtv, 1.0f);
            float bb0 = fminf(fmaxf(dtc * bc[j].x, -10.0f), 10.0f);
            float bb1 = fminf(fmaxf(dtc * bc[j].y, -10.0f), 10.0f);
            h0 = fminf(fmaxf(fmaf(e0, h0, bb0 * xv), -100.0f), 100.0f);
            h1 = fminf(fmaxf(fmaf(e1, h1, bb1 * xv), -100.0f), 100.0f);
            p[j] = fmaf(h1, bc[j].w, h0 * bc[j].z);
        }

        // ---- phase 2: 3-round butterfly over the 8-lane group, round-major ----
#pragma unroll
        for (int s = 1; s < 8; s <<= 1) {
#pragma unroll
            for (int j = 0; j < SCAN_U; j++)
                p[j] += __shfl_xor_sync(0xffffffffu, p[j], s, 32);
        }

        // ---- phase 3: stores (lane n==0 of each channel group) ----
        if (n == 0) {
#pragma unroll
            for (int j = 0; j < SCAN_U; j++) {
                float yo = fminf(fmaxf(fmaf(Dv, xc[j].x, p[j]), -50.0f), 50.0f);
                op[(size_t)(t * SCAN_U + j) * DMODEL] = yo;
            }
        }
    }
}

// ---------------------------------------------------------------------------
extern "C" void kernel_launch(void* const* d_in, const int* in_sizes, int n_in,
                              void* d_out, int out_size) {
    const float* x      = (const float*)d_in[0];
    const float* A_log  = (const float*)d_in[1];
    const float* D_par  = (const float*)d_in[2];
    const float* W_dt1  = (const float*)d_in[3];
    const float* W_dt2  = (const float*)d_in[4];
    const float* b_dt   = (const float*)d_in[5];
    const float* W_B    = (const float*)d_in[6];
    const float* W_C    = (const float*)d_in[7];
    const float* conv_w = (const float*)d_in[8];
    const float* conv_b = (const float*)d_in[9];
    float* out = (float*)d_out;

    (void)in_sizes; (void)n_in; (void)out_size;

    gemm1_kernel<<<MROWS / 64, 384>>>(x, W_dt1, W_B, W_C, conv_w, conv_b);
    gemm2_kernel<<<dim3(MROWS / 64, DMODEL / 64), 256>>>(W_dt2, b_dt);
    scan_kernel<<<(BATCH * DMODEL) / 16, 128>>>(A_log, D_par, out);
}

// round 6
// speedup vs baseline: 1.2927x; 1.2927x over previous
#include <cuda_runtime.h>
#include <cuda_bf16.h>
#include <math.h>

#define BATCH 2
#define LSEQ 4096
#define DMODEL 1024
#define NSTATE 16
#define RRANK 64
#define MROWS (BATCH * LSEQ)   /* 8192 */

// Scratch (static device globals — no allocation at runtime)
__device__ __align__(16) float  g_xconv[MROWS * DMODEL];    // (B,L,D)  32 MB
__device__ __align__(16) float2 g_xdt[MROWS * DMODEL];      // packed {x_conv, dt} 64 MB
__device__ __align__(16) float  g_tmp[MROWS * RRANK];       // (B*L, R)  2 MB
// per row: 8 groups of 4 floats: group n = {B_n, B_{n+8}, C_n, C_{n+8}}
__device__ __align__(16) float g_bc[MROWS * 32];            // 1 MB

// ---------------------------------------------------------------------------
// Kernel 1: depthwise causal conv (K=4) + bias + SiLU, float4 over D.
// One thread = 4 consecutive channels of one row.
// ---------------------------------------------------------------------------
__global__ void conv_silu_kernel(const float4* __restrict__ x4,
                                 const float4* __restrict__ w4,   // (D,4) taps
                                 const float4* __restrict__ bias4) {
    int gid = blockIdx.x * blockDim.x + threadIdx.x;   // row*256 + d4
    if (gid >= MROWS * (DMODEL / 4)) return;
    int d4  = gid & 255;
    int row = gid >> 8;
    int l   = row & (LSEQ - 1);

    // taps for channels 4*d4 .. 4*d4+3
    float4 w0 = __ldg(w4 + d4 * 4 + 0);
    float4 w1 = __ldg(w4 + d4 * 4 + 1);
    float4 w2 = __ldg(w4 + d4 * 4 + 2);
    float4 w3 = __ldg(w4 + d4 * 4 + 3);
    float t0[4] = {w0.x, w0.y, w0.z, w0.w};
    float t1[4] = {w1.x, w1.y, w1.z, w1.w};
    float t2[4] = {w2.x, w2.y, w2.z, w2.w};
    float t3[4] = {w3.x, w3.y, w3.z, w3.w};

    float4 acc = __ldg(bias4 + d4);
#pragma unroll
    for (int k = 0; k < 4; k++) {
        if (l - 3 + k >= 0) {
            float4 xv = __ldg(x4 + (size_t)(row - 3 + k) * 256 + d4);
            acc.x = fmaf(xv.x, t0[k], acc.x);
            acc.y = fmaf(xv.y, t1[k], acc.y);
            acc.z = fmaf(xv.z, t2[k], acc.z);
            acc.w = fmaf(xv.w, t3[k], acc.w);
        }
    }
    acc.x /= (1.0f + __expf(-acc.x));
    acc.y /= (1.0f + __expf(-acc.y));
    acc.z /= (1.0f + __expf(-acc.z));
    acc.w /= (1.0f + __expf(-acc.w));
    reinterpret_cast<float4*>(g_xconv)[gid] = acc;
}

// ---------------------------------------------------------------------------
// Kernel 2: projection GEMM  out(8192 x 96) = x_conv @ [W_dt1; W_B; W_C]^T
// BM=32, BN=96, BK=32, 256 threads, thread tile 2x6, grid 256.
// Register-prefetch double-buffered smem; ONE syncthreads per k-tile.
// ---------------------------------------------------------------------------
__global__ __launch_bounds__(256) void gemm1_kernel(
        const float* __restrict__ Wdt1,
        const float* __restrict__ WB,
        const float* __restrict__ WC) {
    __shared__ float As[2][32][33];     // [buf][k][m]
    __shared__ float Bs[2][32][101];    // [buf][k][j]

    int m0 = blockIdx.x * 32;
    int tid = threadIdx.x;
    int tx = tid & 15;          // 16 col groups * 6 = 96
    int ty = tid >> 4;          // 16 row groups * 2 = 32

    int lr = tid >> 5;          // 0..7 : base row/j for loads
    int lc = tid & 31;          // k-col for loads

    const float* xbase = g_xconv + (size_t)(m0 + lr) * DMODEL + lc;

    float ra[4], rb[12];

    // ---- prefetch tile 0 into registers ----
#pragma unroll
    for (int p = 0; p < 4; p++)
        ra[p] = xbase[p * 8 * DMODEL];
#pragma unroll
    for (int p = 0; p < 12; p++) {
        int j = lr + p * 8;
        const float* wsrc = (j < 64) ? (Wdt1 + j * DMODEL)
                          : (j < 80) ? (WB + (j - 64) * DMODEL)
                                     : (WC + (j - 80) * DMODEL);
        rb[p] = wsrc[lc];
    }

    // store tile 0 to buffer 0
#pragma unroll
    for (int p = 0; p < 4; p++)  As[0][lc][lr + p * 8] = ra[p];
#pragma unroll
    for (int p = 0; p < 12; p++) Bs[0][lc][lr + p * 8] = rb[p];
    __syncthreads();

    float acc[2][6];
#pragma unroll
    for (int i = 0; i < 2; i++)
#pragma unroll
        for (int j = 0; j < 6; j++) acc[i][j] = 0.0f;

    const int NK = DMODEL / 32;
    for (int kt = 0; kt < NK; kt++) {
        int cur = kt & 1;
        // ---- issue loads for tile kt+1 (latency hidden by compute) ----
        if (kt + 1 < NK) {
            int kk = (kt + 1) * 32;
#pragma unroll
            for (int p = 0; p < 4; p++)
                ra[p] = xbase[kk + p * 8 * DMODEL];
#pragma unroll
            for (int p = 0; p < 12; p++) {
                int j = lr + p * 8;
                const float* wsrc = (j < 64) ? (Wdt1 + j * DMODEL)
                                  : (j < 80) ? (WB + (j - 64) * DMODEL)
                                             : (WC + (j - 80) * DMODEL);
                rb[p] = wsrc[kk + lc];
            }
        }

        // ---- compute on buffer cur ----
#pragma unroll
        for (int k = 0; k < 32; k++) {
            float a0 = As[cur][k][ty * 2 + 0];
            float a1 = As[cur][k][ty * 2 + 1];
            float b[6];
#pragma unroll
            for (int j = 0; j < 6; j++) b[j] = Bs[cur][k][tx * 6 + j];
#pragma unroll
            for (int j = 0; j < 6; j++) {
                acc[0][j] = fmaf(a0, b[j], acc[0][j]);
                acc[1][j] = fmaf(a1, b[j], acc[1][j]);
            }
        }

        // ---- store prefetched tile into other buffer ----
        if (kt + 1 < NK) {
            int nxt = (kt + 1) & 1;
#pragma unroll
            for (int p = 0; p < 4; p++)  As[nxt][lc][lr + p * 8] = ra[p];
#pragma unroll
            for (int p = 0; p < 12; p++) Bs[nxt][lc][lr + p * 8] = rb[p];
            __syncthreads();
        }
    }

    // ---- epilogue ----
#pragma unroll
    for (int i = 0; i < 2; i++) {
        int row = m0 + ty * 2 + i;
#pragma unroll
        for (int j = 0; j < 6; j++) {
            int col = tx * 6 + j;
            float v = acc[i][j];
            if (col < 64) {
                g_tmp[row * RRANK + col] = v;
            } else if (col < 80) {
                int s = col - 64;   // B state s
                g_bc[row * 32 + (s & 7) * 4 + (s >> 3)] = v;
            } else {
                int s = col - 80;   // C state s
                g_bc[row * 32 + (s & 7) * 4 + 2 + (s >> 3)] = v;
            }
        }
    }
}

// ---------------------------------------------------------------------------
// Kernel 3: dt = softplus(g_tmp @ W_dt2^T + b_dt)   M=8192, N=1024, K=64
// Writes packed {x_conv, dt} into g_xdt with coalesced 16B stores.
// ---------------------------------------------------------------------------
__global__ void gemm2_kernel(const float* __restrict__ Wdt2,
                             const float* __restrict__ bdt) {
    __shared__ float As[64][65];    // [k][m]
    __shared__ float Bs[64][68];    // [k][d]

    int m0 = blockIdx.x * 64;
    int n0 = blockIdx.y * 64;
    int tid = threadIdx.x;
    int tx = tid % 16;
    int ty = tid / 16;

    for (int e = tid; e < 64 * 64; e += 256) {
        int r = e >> 6, c = e & 63;
        As[c][r] = g_tmp[(m0 + r) * RRANK + c];
        Bs[c][r] = Wdt2[(n0 + r) * RRANK + c];
    }
    __syncthreads();

    float acc[4][4];
#pragma unroll
    for (int i = 0; i < 4; i++)
#pragma unroll
        for (int j = 0; j < 4; j++) acc[i][j] = 0.0f;

#pragma unroll
    for (int k = 0; k < 64; k++) {
        float a[4], b[4];
#pragma unroll
        for (int i = 0; i < 4; i++) a[i] = As[k][ty * 4 + i];
#pragma unroll
        for (int j = 0; j < 4; j++) b[j] = Bs[k][tx * 4 + j];
#pragma unroll
        for (int i = 0; i < 4; i++)
#pragma unroll
            for (int j = 0; j < 4; j++)
                acc[i][j] = fmaf(a[i], b[j], acc[i][j]);
    }

#pragma unroll
    for (int i = 0; i < 4; i++) {
        int row = m0 + ty * 4 + i;
        int col0 = n0 + tx * 4;
        float4 xv = *reinterpret_cast<const float4*>(&g_xconv[row * DMODEL + col0]);
        float sp[4];
#pragma unroll
        for (int j = 0; j < 4; j++) {
            float z = acc[i][j] + bdt[col0 + j];
            sp[j] = fmaxf(z, 0.0f) + log1pf(__expf(-fabsf(z)));   // softplus
        }
        float4* dst = reinterpret_cast<float4*>(&g_xdt[row * DMODEL + col0]);
        dst[0] = make_float4(xv.x, sp[0], xv.y, sp[1]);
        dst[1] = make_float4(xv.z, sp[2], xv.w, sp[3]);
    }
}

// ---------------------------------------------------------------------------
// Kernel 4: selective scan.
// 8 lanes per channel, 2 states per thread (n and n+8) -> warp = 4 channels.
// 3-round butterfly (round-major), software-pipelined loads.
// ---------------------------------------------------------------------------
#define SCAN_U 8

__global__ __launch_bounds__(128) void scan_kernel(
        const float* __restrict__ A_log,
        const float* __restrict__ Dp,
        float* __restrict__ out) {
    int tid = threadIdx.x;
    int lane = tid & 31;
    int warp = tid >> 5;
    int n = lane & 7;                      // state index (this thread: n, n+8)
    int c = blockIdx.x * 16 + warp * 4 + (lane >> 3);   // channel = b*D + d
    int b = c >> 10;
    int d = c & (DMODEL - 1);

    float A0 = -__expf(A_log[d * NSTATE + n]);
    float A1 = -__expf(A_log[d * NSTATE + n + 8]);
    float Dv = Dp[d];

    const float2* xdtp = g_xdt + (size_t)b * LSEQ * DMODEL + d;
    const float4* bcp  = reinterpret_cast<const float4*>(g_bc)
                         + (size_t)b * LSEQ * 8 + n;
    float* op = out + (size_t)b * LSEQ * DMODEL + d;

    float h0 = 0.0f, h1 = 0.0f;

    float2 xn[SCAN_U];
    float4 bn[SCAN_U];
#pragma unroll
    for (int j = 0; j < SCAN_U; j++) {
        xn[j] = __ldg(xdtp + j * DMODEL);
        bn[j] = __ldg(bcp + j * 8);
    }
    xdtp += SCAN_U * DMODEL;
    bcp  += SCAN_U * 8;

    const int NTILES = LSEQ / SCAN_U;
    for (int t = 0; t < NTILES; t++) {
        float2 xc[SCAN_U];
        float4 bc[SCAN_U];
#pragma unroll
        for (int j = 0; j < SCAN_U; j++) { xc[j] = xn[j]; bc[j] = bn[j]; }

        if (t + 1 < NTILES) {
#pragma unroll
            for (int j = 0; j < SCAN_U; j++) {
                xn[j] = __ldg(xdtp + j * DMODEL);
                bn[j] = __ldg(bcp + j * 8);
            }
            xdtp += SCAN_U * DMODEL;
            bcp  += SCAN_U * 8;
        }

        float p[SCAN_U];
#pragma unroll
        for (int j = 0; j < SCAN_U; j++) {
            float xv  = xc[j].x;
            float dtv = xc[j].y;
            float e0 = fminf(__expf(fmaxf(dtv * A0, -10.0f)), 0.999f);
            float e1 = fminf(__expf(fmaxf(dtv * A1, -10.0f)), 0.999f);
            float dtc = fminf(dtv, 1.0f);
            float bb0 = fminf(fmaxf(dtc * bc[j].x, -10.0f), 10.0f);
            float bb1 = fminf(fmaxf(dtc * bc[j].y, -10.0f), 10.0f);
            h0 = fminf(fmaxf(fmaf(e0, h0, bb0 * xv), -100.0f), 100.0f);
            h1 = fminf(fmaxf(fmaf(e1, h1, bb1 * xv), -100.0f), 100.0f);
            p[j] = fmaf(h1, bc[j].w, h0 * bc[j].z);
        }

#pragma unroll
        for (int s = 1; s < 8; s <<= 1) {
#pragma unroll
            for (int j = 0; j < SCAN_U; j++)
                p[j] += __shfl_xor_sync(0xffffffffu, p[j], s, 32);
        }

        if (n == 0) {
#pragma unroll
            for (int j = 0; j < SCAN_U; j++) {
                float yo = fminf(fmaxf(fmaf(Dv, xc[j].x, p[j]), -50.0f), 50.0f);
                op[(size_t)(t * SCAN_U + j) * DMODEL] = yo;
            }
        }
    }
}

// ---------------------------------------------------------------------------
extern "C" void kernel_launch(void* const* d_in, const int* in_sizes, int n_in,
                              void* d_out, int out_size) {
    const float* x      = (const float*)d_in[0];
    const float* A_log  = (const float*)d_in[1];
    const float* D_par  = (const float*)d_in[2];
    const float* W_dt1  = (const float*)d_in[3];
    const float* W_dt2  = (const float*)d_in[4];
    const float* b_dt   = (const float*)d_in[5];
    const float* W_B    = (const float*)d_in[6];
    const float* W_C    = (const float*)d_in[7];
    const float* conv_w = (const float*)d_in[8];
    const float* conv_b = (const float*)d_in[9];
    float* out = (float*)d_out;

    (void)in_sizes; (void)n_in; (void)out_size;

    int tot4 = MROWS * (DMODEL / 4);
    conv_silu_kernel<<<(tot4 + 255) / 256, 256>>>(
        (const float4*)x, (const float4*)conv_w, (const float4*)conv_b);
    gemm1_kernel<<<MROWS / 32, 256>>>(W_dt1, W_B, W_C);
    gemm2_kernel<<<dim3(MROWS / 64, DMODEL / 64), 256>>>(W_dt2, b_dt);
    scan_kernel<<<(BATCH * DMODEL) / 16, 128>>>(A_log, D_par, out);
}

// round 7
// speedup vs baseline: 1.4808x; 1.1455x over previous
#include <cuda_runtime.h>
#include <cuda_bf16.h>
#include <math.h>

#define BATCH 2
#define LSEQ 4096
#define DMODEL 1024
#define NSTATE 16
#define RRANK 64
#define MROWS (BATCH * LSEQ)   /* 8192 */

// Scratch (static device globals — no allocation at runtime)
__device__ __align__(16) float  g_xconv[MROWS * DMODEL];    // (B,L,D)  32 MB
__device__ __align__(16) float2 g_xdt[MROWS * DMODEL];      // packed {x_conv, dt} 64 MB
__device__ __align__(16) float  g_tmp[MROWS * RRANK];       // (B*L, R)  2 MB
// per row: 8 groups of 4 floats: group n = {B_n, B_{n+8}, C_n, C_{n+8}}
__device__ __align__(16) float g_bc[MROWS * 32];            // 1 MB

// ---------------------------------------------------------------------------
// Kernel 1: depthwise causal conv (K=4) + bias + SiLU, float4 over D.
// ---------------------------------------------------------------------------
__global__ void conv_silu_kernel(const float4* __restrict__ x4,
                                 const float4* __restrict__ w4,
                                 const float4* __restrict__ bias4) {
    int gid = blockIdx.x * blockDim.x + threadIdx.x;   // row*256 + d4
    if (gid >= MROWS * (DMODEL / 4)) return;
    int d4  = gid & 255;
    int row = gid >> 8;
    int l   = row & (LSEQ - 1);

    float4 w0 = __ldg(w4 + d4 * 4 + 0);
    float4 w1 = __ldg(w4 + d4 * 4 + 1);
    float4 w2 = __ldg(w4 + d4 * 4 + 2);
    float4 w3 = __ldg(w4 + d4 * 4 + 3);
    float t0[4] = {w0.x, w0.y, w0.z, w0.w};
    float t1[4] = {w1.x, w1.y, w1.z, w1.w};
    float t2[4] = {w2.x, w2.y, w2.z, w2.w};
    float t3[4] = {w3.x, w3.y, w3.z, w3.w};

    float4 acc = __ldg(bias4 + d4);
#pragma unroll
    for (int k = 0; k < 4; k++) {
        if (l - 3 + k >= 0) {
            float4 xv = __ldg(x4 + (size_t)(row - 3 + k) * 256 + d4);
            acc.x = fmaf(xv.x, t0[k], acc.x);
            acc.y = fmaf(xv.y, t1[k], acc.y);
            acc.z = fmaf(xv.z, t2[k], acc.z);
            acc.w = fmaf(xv.w, t3[k], acc.w);
        }
    }
    acc.x /= (1.0f + __expf(-acc.x));
    acc.y /= (1.0f + __expf(-acc.y));
    acc.z /= (1.0f + __expf(-acc.z));
    acc.w /= (1.0f + __expf(-acc.w));
    reinterpret_cast<float4*>(g_xconv)[gid] = acc;
}

// ---------------------------------------------------------------------------
// Kernel 2: projection GEMM  out(8192 x 96) = x_conv @ [W_dt1; W_B; W_C]^T
// BM=32, BN=96, BK=32, 256 threads, double-buffered, grid 256.
// ---------------------------------------------------------------------------
__global__ __launch_bounds__(256) void gemm1_kernel(
        const float* __restrict__ Wdt1,
        const float* __restrict__ WB,
        const float* __restrict__ WC) {
    __shared__ float As[2][32][33];     // [buf][k][m]
    __shared__ float Bs[2][32][101];    // [buf][k][j]

    int m0 = blockIdx.x * 32;
    int tid = threadIdx.x;
    int tx = tid & 15;          // 16 col groups * 6 = 96
    int ty = tid >> 4;          // 16 row groups * 2 = 32

    int lr = tid >> 5;          // 0..7
    int lc = tid & 31;          // k-col

    const float* xbase = g_xconv + (size_t)(m0 + lr) * DMODEL + lc;

    float ra[4], rb[12];

#pragma unroll
    for (int p = 0; p < 4; p++)
        ra[p] = xbase[p * 8 * DMODEL];
#pragma unroll
    for (int p = 0; p < 12; p++) {
        int j = lr + p * 8;
        const float* wsrc = (j < 64) ? (Wdt1 + j * DMODEL)
                          : (j < 80) ? (WB + (j - 64) * DMODEL)
                                     : (WC + (j - 80) * DMODEL);
        rb[p] = wsrc[lc];
    }

#pragma unroll
    for (int p = 0; p < 4; p++)  As[0][lc][lr + p * 8] = ra[p];
#pragma unroll
    for (int p = 0; p < 12; p++) Bs[0][lc][lr + p * 8] = rb[p];
    __syncthreads();

    float acc[2][6];
#pragma unroll
    for (int i = 0; i < 2; i++)
#pragma unroll
        for (int j = 0; j < 6; j++) acc[i][j] = 0.0f;

    const int NK = DMODEL / 32;
    for (int kt = 0; kt < NK; kt++) {
        int cur = kt & 1;
        if (kt + 1 < NK) {
            int kk = (kt + 1) * 32;
#pragma unroll
            for (int p = 0; p < 4; p++)
                ra[p] = xbase[kk + p * 8 * DMODEL];
#pragma unroll
            for (int p = 0; p < 12; p++) {
                int j = lr + p * 8;
                const float* wsrc = (j < 64) ? (Wdt1 + j * DMODEL)
                                  : (j < 80) ? (WB + (j - 64) * DMODEL)
                                             : (WC + (j - 80) * DMODEL);
                rb[p] = wsrc[kk + lc];
            }
        }

#pragma unroll
        for (int k = 0; k < 32; k++) {
            float a0 = As[cur][k][ty * 2 + 0];
            float a1 = As[cur][k][ty * 2 + 1];
            float b[6];
#pragma unroll
            for (int j = 0; j < 6; j++) b[j] = Bs[cur][k][tx * 6 + j];
#pragma unroll
            for (int j = 0; j < 6; j++) {
                acc[0][j] = fmaf(a0, b[j], acc[0][j]);
                acc[1][j] = fmaf(a1, b[j], acc[1][j]);
            }
        }

        if (kt + 1 < NK) {
            int nxt = (kt + 1) & 1;
#pragma unroll
            for (int p = 0; p < 4; p++)  As[nxt][lc][lr + p * 8] = ra[p];
#pragma unroll
            for (int p = 0; p < 12; p++) Bs[nxt][lc][lr + p * 8] = rb[p];
            __syncthreads();
        }
    }

#pragma unroll
    for (int i = 0; i < 2; i++) {
        int row = m0 + ty * 2 + i;
#pragma unroll
        for (int j = 0; j < 6; j++) {
            int col = tx * 6 + j;
            float v = acc[i][j];
            if (col < 64) {
                g_tmp[row * RRANK + col] = v;
            } else if (col < 80) {
                int s = col - 64;   // B state s
                g_bc[row * 32 + (s & 7) * 4 + (s >> 3)] = v;
            } else {
                int s = col - 80;   // C state s
                g_bc[row * 32 + (s & 7) * 4 + 2 + (s >> 3)] = v;
            }
        }
    }
}

// ---------------------------------------------------------------------------
// Kernel 3: dt = softplus(g_tmp @ W_dt2^T + b_dt); packs {x, dt} into g_xdt.
// ---------------------------------------------------------------------------
__global__ void gemm2_kernel(const float* __restrict__ Wdt2,
                             const float* __restrict__ bdt) {
    __shared__ float As[64][65];
    __shared__ float Bs[64][68];

    int m0 = blockIdx.x * 64;
    int n0 = blockIdx.y * 64;
    int tid = threadIdx.x;
    int tx = tid % 16;
    int ty = tid / 16;

    for (int e = tid; e < 64 * 64; e += 256) {
        int r = e >> 6, c = e & 63;
        As[c][r] = g_tmp[(m0 + r) * RRANK + c];
        Bs[c][r] = Wdt2[(n0 + r) * RRANK + c];
    }
    __syncthreads();

    float acc[4][4];
#pragma unroll
    for (int i = 0; i < 4; i++)
#pragma unroll
        for (int j = 0; j < 4; j++) acc[i][j] = 0.0f;

#pragma unroll
    for (int k = 0; k < 64; k++) {
        float a[4], b[4];
#pragma unroll
        for (int i = 0; i < 4; i++) a[i] = As[k][ty * 4 + i];
#pragma unroll
        for (int j = 0; j < 4; j++) b[j] = Bs[k][tx * 4 + j];
#pragma unroll
        for (int i = 0; i < 4; i++)
#pragma unroll
            for (int j = 0; j < 4; j++)
                acc[i][j] = fmaf(a[i], b[j], acc[i][j]);
    }

#pragma unroll
    for (int i = 0; i < 4; i++) {
        int row = m0 + ty * 4 + i;
        int col0 = n0 + tx * 4;
        float4 xv = *reinterpret_cast<const float4*>(&g_xconv[row * DMODEL + col0]);
        float sp[4];
#pragma unroll
        for (int j = 0; j < 4; j++) {
            float z = acc[i][j] + bdt[col0 + j];
            sp[j] = fmaxf(z, 0.0f) + log1pf(__expf(-fabsf(z)));   // softplus
        }
        float4* dst = reinterpret_cast<float4*>(&g_xdt[row * DMODEL + col0]);
        dst[0] = make_float4(xv.x, sp[0], xv.y, sp[1]);
        dst[1] = make_float4(xv.z, sp[2], xv.w, sp[3]);
    }
}

// ---------------------------------------------------------------------------
// Kernel 4: selective scan — 2-tile unrolled cross-tile software pipeline.
// 8 lanes/channel, 2 states/thread; warp = 4 channels; 512 warps total.
// Butterfly+store of tile t-1 deferred past phase1 of tile t (independent),
// hiding shfl latency under the fma stream. D*x folded pre-reduction.
// ---------------------------------------------------------------------------
#define SCAN_U 8
#define NEG10_LOG2E (-14.4269504f)

__global__ __launch_bounds__(64) void scan_kernel(
        const float* __restrict__ A_log,
        const float* __restrict__ Dp,
        float* __restrict__ out) {
    const float LOG2E = 1.4426950408889634f;
    int tid = threadIdx.x;
    int lane = tid & 31;
    int n = lane & 7;                              // state pair (n, n+8)
    int c = blockIdx.x * 8 + (tid >> 5) * 4 + (lane >> 3);
    int b = c >> 10;
    int d = c & (DMODEL - 1);

    float A0 = -__expf(A_log[d * NSTATE + n]) * LOG2E;
    float A1 = -__expf(A_log[d * NSTATE + n + 8]) * LOG2E;
    float Dv0 = (n == 0) ? Dp[d] : 0.0f;           // folded pre-reduction

    const float2* xbase = g_xdt + (size_t)b * LSEQ * DMODEL + d;
    const float4* bbase = reinterpret_cast<const float4*>(g_bc)
                          + (size_t)b * LSEQ * 8 + n;
    float* op = out + (size_t)b * LSEQ * DMODEL + d;

    float h0 = 0.0f, h1 = 0.0f;
    float2 xA[SCAN_U], xB[SCAN_U];
    float4 bA[SCAN_U], bB[SCAN_U];
    float  pA[SCAN_U], pB[SCAN_U];

    // prefetch tile 0 -> A
#pragma unroll
    for (int j = 0; j < SCAN_U; j++) {
        xA[j] = __ldg(xbase + j * DMODEL);
        bA[j] = __ldg(bbase + j * 8);
    }

    const int NT = LSEQ / SCAN_U;   // 512
    for (int t = 0; t < NT; t += 2) {
        // ---- butterfly for tile t-1 (pB), shfls issue early ----
        if (t) {
#pragma unroll
            for (int s = 1; s < 8; s <<= 1)
#pragma unroll
                for (int j = 0; j < SCAN_U; j++)
                    pB[j] += __shfl_xor_sync(0xffffffffu, pB[j], s, 32);
        }
        // ---- prefetch tile t+1 -> B ----
        {
            const float2* xp = xbase + (size_t)(t + 1) * SCAN_U * DMODEL;
            const float4* bp = bbase + (size_t)(t + 1) * SCAN_U * 8;
#pragma unroll
            for (int j = 0; j < SCAN_U; j++) {
                xB[j] = __ldg(xp + j * DMODEL);
                bB[j] = __ldg(bp + j * 8);
            }
        }
        // ---- phase1 tile t (from A); hides shfl + load latency ----
#pragma unroll
        for (int j = 0; j < SCAN_U; j++) {
            float xv = xA[j].x, dtv = xA[j].y;
            float e0 = fminf(exp2f(fmaxf(dtv * A0, NEG10_LOG2E)), 0.999f);
            float e1 = fminf(exp2f(fmaxf(dtv * A1, NEG10_LOG2E)), 0.999f);
            float dtc = fminf(dtv, 1.0f);
            float bb0 = fminf(fmaxf(dtc * bA[j].x, -10.0f), 10.0f);
            float bb1 = fminf(fmaxf(dtc * bA[j].y, -10.0f), 10.0f);
            h0 = fminf(fmaxf(fmaf(e0, h0, bb0 * xv), -100.0f), 100.0f);
            h1 = fminf(fmaxf(fmaf(e1, h1, bb1 * xv), -100.0f), 100.0f);
            float p = fmaf(h1, bA[j].w, h0 * bA[j].z);
            pA[j] = fmaf(Dv0, xv, p);
        }
        // ---- store tile t-1 ----
        if (t && n == 0) {
#pragma unroll
            for (int j = 0; j < SCAN_U; j++)
                op[(size_t)((t - 1) * SCAN_U + j) * DMODEL] =
                    fminf(fmaxf(pB[j], -50.0f), 50.0f);
        }
        // ---- butterfly for tile t (pA) ----
#pragma unroll
        for (int s = 1; s < 8; s <<= 1)
#pragma unroll
            for (int j = 0; j < SCAN_U; j++)
                pA[j] += __shfl_xor_sync(0xffffffffu, pA[j], s, 32);
        // ---- prefetch tile t+2 -> A ----
        if (t + 2 < NT) {
            const float2* xp = xbase + (size_t)(t + 2) * SCAN_U * DMODEL;
            const float4* bp = bbase + (size_t)(t + 2) * SCAN_U * 8;
#pragma unroll
            for (int j = 0; j < SCAN_U; j++) {
                xA[j] = __ldg(xp + j * DMODEL);
                bA[j] = __ldg(bp + j * 8);
            }
        }
        // ---- phase1 tile t+1 (from B) ----
#pragma unroll
        for (int j = 0; j < SCAN_U; j++) {
            float xv = xB[j].x, dtv = xB[j].y;
            float e0 = fminf(exp2f(fmaxf(dtv * A0, NEG10_LOG2E)), 0.999f);
            float e1 = fminf(exp2f(fmaxf(dtv * A1, NEG10_LOG2E)), 0.999f);
            float dtc = fminf(dtv, 1.0f);
            float bb0 = fminf(fmaxf(dtc * bB[j].x, -10.0f), 10.0f);
            float bb1 = fminf(fmaxf(dtc * bB[j].y, -10.0f), 10.0f);
            h0 = fminf(fmaxf(fmaf(e0, h0, bb0 * xv), -100.0f), 100.0f);
            h1 = fminf(fmaxf(fmaf(e1, h1, bb1 * xv), -100.0f), 100.0f);
            float p = fmaf(h1, bB[j].w, h0 * bB[j].z);
            pB[j] = fmaf(Dv0, xv, p);
        }
        // ---- store tile t ----
        if (n == 0) {
#pragma unroll
            for (int j = 0; j < SCAN_U; j++)
                op[(size_t)(t * SCAN_U + j) * DMODEL] =
                    fminf(fmaxf(pA[j], -50.0f), 50.0f);
        }
    }

    // epilogue: reduce + store last tile (NT-1) held in pB
#pragma unroll
    for (int s = 1; s < 8; s <<= 1)
#pragma unroll
        for (int j = 0; j < SCAN_U; j++)
            pB[j] += __shfl_xor_sync(0xffffffffu, pB[j], s, 32);
    if (n == 0) {
#pragma unroll
        for (int j = 0; j < SCAN_U; j++)
            op[(size_t)((NT - 1) * SCAN_U + j) * DMODEL] =
                fminf(fmaxf(pB[j], -50.0f), 50.0f);
    }
}

// ---------------------------------------------------------------------------
extern "C" void kernel_launch(void* const* d_in, const int* in_sizes, int n_in,
                              void* d_out, int out_size) {
    const float* x      = (const float*)d_in[0];
    const float* A_log  = (const float*)d_in[1];
    const float* D_par  = (const float*)d_in[2];
    const float* W_dt1  = (const float*)d_in[3];
    const float* W_dt2  = (const float*)d_in[4];
    const float* b_dt   = (const float*)d_in[5];
    const float* W_B    = (const float*)d_in[6];
    const float* W_C    = (const float*)d_in[7];
    const float* conv_w = (const float*)d_in[8];
    const float* conv_b = (const float*)d_in[9];
    float* out = (float*)d_out;

    (void)in_sizes; (void)n_in; (void)out_size;

    int tot4 = MROWS * (DMODEL / 4);
    conv_silu_kernel<<<(tot4 + 255) / 256, 256>>>(
        (const float4*)x, (const float4*)conv_w, (const float4*)conv_b);
    gemm1_kernel<<<MROWS / 32, 256>>>(W_dt1, W_B, W_C);
    gemm2_kernel<<<dim3(MROWS / 64, DMODEL / 64), 256>>>(W_dt2, b_dt);
    scan_kernel<<<(BATCH * DMODEL) / 8, 64>>>(A_log, D_par, out);
}